// round 16
// baseline (speedup 1.0000x reference)
#include <cuda_runtime.h>
#include <stdint.h>

// Fixed problem shapes
#define NB 32
#define NS 32
#define NW 30
#define NE 300
#define NEV 75                   // float4 per embedding row (300 floats)
#define NSENT (NB * NS)          // 1024
#define EMB_ELEMS (NSENT * NW * NE)          // 9,216,000
#define OFF_SHARE  EMB_ELEMS
#define OFF_MASK   (2 * EMB_ELEMS)           // 18,432,000
#define OFF_WMASK  (OFF_MASK + NSENT * NW)
#define OFF_SMASK  (OFF_WMASK + NSENT * NW)

#define SENT_VEC  (NW * NEV)     // 2250 float4 per sentence
#define BLOCK     256
#define NITER     9              // 8 full + 1 tail (202 lanes); MLP=9 per thread

__global__ __launch_bounds__(BLOCK) void embed_fused_kernel(
    const int* __restrict__ input_var,        // [1024*30] int32 tokens
    const float* __restrict__ W_emb,          // [50000*300]
    float* __restrict__ out)
{
    const int sent = blockIdx.x;        // 0..1023
    const int tid  = threadIdx.x;

    __shared__ int s_tok[NW];
    __shared__ unsigned s_kmask;        // bit w set => token w kept (before first zero)

    // Warp 0: load tokens + compute all masks with one ballot
    if (tid < 32) {
        const int t = (tid < NW) ? input_var[sent * NW + tid] : 1;
        if (tid < NW) s_tok[tid] = t;
        const unsigned nz = __ballot_sync(0xFFFFFFFFu, t != 0);
        const unsigned firstzero = ~nz;                 // lowest set bit = first zero
        const unsigned keepmask  = (firstzero - 1u) & ~firstzero & 0x3FFFFFFFu;
        if (tid == 0) s_kmask = keepmask;
        if (tid < NW) {
            out[OFF_MASK  + sent * NW + tid] = (keepmask >> tid & 1u) ? 1.0f : 0.0f;
            out[OFF_WMASK + sent * NW + tid] = (t != 0) ? 1.0f : 0.0f;
        }
        if (tid == 0) {
            out[OFF_SMASK + sent] = ((nz & 0x3FFFFFFFu) != 0u) ? 1.0f : 0.0f;
        }
    }
    __syncthreads();

    const unsigned kmask = s_kmask;
    const float4* __restrict__ emb4 = (const float4*)W_emb;
    float4* __restrict__ out_e = (float4*)out + (size_t)sent * SENT_VEC;
    float4* __restrict__ out_s = (float4*)(out + OFF_SHARE) + (size_t)sent * SENT_VEC;

    // Phase 1: 9-deep batched gathers. i=0..7 provably in-bounds
    // (tid + 7*256 <= 2047 < 2250); only the tail is predicated.
    float4 vals[NITER];
    #pragma unroll
    for (int i = 0; i < 8; i++) {
        const int v = tid + i * BLOCK;
        const int w = v / NEV;
        const int j = v - w * NEV;
        vals[i] = __ldg(&emb4[(size_t)s_tok[w] * NEV + j]);
    }
    {
        const int v = tid + 8 * BLOCK;
        if (v < SENT_VEC) {
            const int w = v / NEV;
            const int j = v - w * NEV;
            vals[8] = __ldg(&emb4[(size_t)s_tok[w] * NEV + j]);
        }
    }

    // Phase 2: block-uniform fast path (all 30 rows kept, ~99.9% of sentences)
    if ((kmask & 0x3FFFFFFFu) == 0x3FFFFFFFu) {
        #pragma unroll
        for (int i = 0; i < NITER; i++) {
            const int v = tid + i * BLOCK;
            if (i < 8 || v < SENT_VEC) {
                __stcs(&out_e[v], vals[i]);
                __stcs(&out_s[v], vals[i]);
            }
        }
    } else {
        // Rare slow path: truncated token -> row 0 (predicated reload)
        #pragma unroll
        for (int i = 0; i < NITER; i++) {
            const int v = tid + i * BLOCK;
            if (i < 8 || v < SENT_VEC) {
                const int w = v / NEV;
                const int j = v - w * NEV;
                __stcs(&out_e[v], vals[i]);
                float4 x = vals[i];
                if (!(kmask >> w & 1u)) x = __ldg(&emb4[j]);   // row 0
                __stcs(&out_s[v], x);
            }
        }
    }
}

extern "C" void kernel_launch(void* const* d_in, const int* in_sizes, int n_in,
                              void* d_out, int out_size) {
    const int*   input_var = (const int*)d_in[0];
    const float* W_emb     = (const float*)d_in[1];
    float*       out       = (float*)d_out;

    embed_fused_kernel<<<NSENT, BLOCK>>>(input_var, W_emb, out);
}

// round 17
// speedup vs baseline: 1.0019x; 1.0019x over previous
#include <cuda_runtime.h>
#include <stdint.h>

// Fixed problem shapes
#define NB 32
#define NS 32
#define NW 30
#define NE 300
#define NEV 75                   // float4 per embedding row (300 floats)
#define NSENT (NB * NS)          // 1024
#define EMB_ELEMS (NSENT * NW * NE)          // 9,216,000
#define OFF_SHARE  EMB_ELEMS
#define OFF_MASK   (2 * EMB_ELEMS)           // 18,432,000
#define OFF_WMASK  (OFF_MASK + NSENT * NW)
#define OFF_SMASK  (OFF_WMASK + NSENT * NW)

#define HALF_ROWS 15
#define HALF_VEC  (HALF_ROWS * NEV)          // 1125 float4 per half-sentence
#define BLOCK     256
#define NITER     5

__global__ __launch_bounds__(BLOCK, 8) void embed_fused_kernel(
    const int* __restrict__ input_var,        // [1024*30] int32 tokens
    const float* __restrict__ W_emb,          // [50000*300]
    float* __restrict__ out)
{
    const int sent = blockIdx.x >> 1;   // 0..1023
    const int half = blockIdx.x & 1;    // 0: rows 0-14, 1: rows 15-29
    const int tid  = threadIdx.x;

    __shared__ int s_tok[NW];
    __shared__ unsigned s_kmask;        // bit w set => token w kept (before first zero)

    // Warp 0: load tokens + compute all masks with one ballot
    if (tid < 32) {
        const int t = (tid < NW) ? input_var[sent * NW + tid] : 1;
        if (tid < NW) s_tok[tid] = t;
        const unsigned nz = __ballot_sync(0xFFFFFFFFu, t != 0);
        const unsigned firstzero = ~nz;                 // lowest set bit = first zero
        const unsigned keepmask  = (firstzero - 1u) & ~firstzero & 0x3FFFFFFFu;
        if (tid == 0) s_kmask = keepmask;
        if (half == 0 && tid < NW) {
            out[OFF_MASK  + sent * NW + tid] = (keepmask >> tid & 1u) ? 1.0f : 0.0f;
            out[OFF_WMASK + sent * NW + tid] = (t != 0) ? 1.0f : 0.0f;
        }
        if (half == 0 && tid == 0) {
            out[OFF_SMASK + sent] = ((nz & 0x3FFFFFFFu) != 0u) ? 1.0f : 0.0f;
        }
    }
    __syncthreads();

    const unsigned kmask = s_kmask;
    const float4* __restrict__ emb4 = (const float4*)W_emb;
    float4* __restrict__ out_e = (float4*)out
        + (size_t)sent * (NW * NEV) + half * HALF_VEC;
    float4* __restrict__ out_s = (float4*)(out + OFF_SHARE)
        + (size_t)sent * (NW * NEV) + half * HALF_VEC;
    const int rbase = half * HALF_ROWS;

    // Phase 1: 5 batched gathers, ALL issued unconditionally (tail index clamped
    // to an in-bounds address; its value is only consumed when v < HALF_VEC).
    float4 vals[NITER];
    #pragma unroll
    for (int i = 0; i < NITER; i++) {
        int v = tid + i * BLOCK;
        if (v >= HALF_VEC) v = HALF_VEC - 1;        // clamp (tail lanes only)
        const int w = v / NEV;
        const int j = v - w * NEV;
        vals[i] = __ldg(&emb4[(size_t)s_tok[rbase + w] * NEV + j]);
    }

    // Phase 2: block-uniform fast path — all rows of this half kept (~99.9%):
    // pure back-to-back streaming stores.
    if (((kmask >> rbase) & 0x7FFFu) == 0x7FFFu) {
        #pragma unroll
        for (int i = 0; i < NITER; i++) {
            const int v = tid + i * BLOCK;
            if (i < 4 || v < HALF_VEC) {
                __stcs(&out_e[v], vals[i]);
                __stcs(&out_s[v], vals[i]);
            }
        }
    } else {
        // Rare slow path: truncated token -> row 0
        #pragma unroll
        for (int i = 0; i < NITER; i++) {
            const int v = tid + i * BLOCK;
            if (i < 4 || v < HALF_VEC) {
                const int w = v / NEV;
                const int j = v - w * NEV;
                __stcs(&out_e[v], vals[i]);
                float4 x = vals[i];
                if (!(kmask >> (rbase + w) & 1u)) x = __ldg(&emb4[j]);   // row 0
                __stcs(&out_s[v], x);
            }
        }
    }
}

extern "C" void kernel_launch(void* const* d_in, const int* in_sizes, int n_in,
                              void* d_out, int out_size) {
    const int*   input_var = (const int*)d_in[0];
    const float* W_emb     = (const float*)d_in[1];
    float*       out       = (float*)d_out;

    embed_fused_kernel<<<2 * NSENT, BLOCK>>>(input_var, W_emb, out);
}